// round 15
// baseline (speedup 1.0000x reference)
#include <cuda_runtime.h>

// Problem constants
#define SEQ      1024
#define BATCH    64
#define IN_DIM   128
#define HID      512
#define ALPHA    0.1f
#define SBH      (BATCH * HID)   // 32768 elements per timestep

// ---------------- persistent recurrent kernel config ----------------
#define R_GRID    128            // 32 h-groups x 4 b-groups, 1 CTA/SM
#define R_THREADS 512            // 16 warps, each owns a k-sixteenth
#define FLAG_STRIDE 32           // unsigneds; 128B apart -> distinct LTS slices

// Smem geometry (float4 units)
#define W_F4    (8 * 257)        // packed W: [hp 0..7][kbg 0..255], stride 257
#define F_F4    (8 * 257)        // packed fr: [bp 0..7][kbg 0..255], stride 257
#define RED_F4  (2 * 16 * 81)    // partials: [buf][u 0..15][sl*5 + b']
#define SMEM_BYTES ((W_F4 + F_F4 + RED_F4) * 16)   // 107264

// fr double buffer (L2-resident, 256 KB) + padded barrier flags
__device__ float    g_fr[2][SBH];
__device__ unsigned g_flags[R_GRID * FLAG_STRIDE];

// ---------------- release/acquire primitives --------------------------------
__device__ __forceinline__ void st_release_gpu(unsigned* p, unsigned v) {
    asm volatile("st.release.gpu.global.u32 [%0], %1;" :: "l"(p), "r"(v) : "memory");
}
__device__ __forceinline__ unsigned ld_acquire_gpu(const unsigned* p) {
    unsigned v;
    asm volatile("ld.acquire.gpu.global.u32 %0, [%1];" : "=r"(v) : "l"(p) : "memory");
    return v;
}

// ---------------- packed f32x2 FMA (FFMA2) ----------------------------------
__device__ __forceinline__ unsigned long long ffma2(
    unsigned long long a, unsigned long long b, unsigned long long c) {
    unsigned long long d;
    asm("fma.rn.f32x2 %0, %1, %2, %3;" : "=l"(d) : "l"(a), "l"(b), "l"(c));
    return d;
}
__device__ __forceinline__ float f32x2_hadd(unsigned long long a) {
    float lo, hi;
    asm("mov.b64 {%0, %1}, %2;" : "=f"(lo), "=f"(hi) : "l"(a));
    return lo + hi;
}
__device__ __forceinline__ float4 shfl_xor_f4(float4 v, int m) {
    v.x += __shfl_xor_sync(0xFFFFFFFFu, v.x, m);
    v.y += __shfl_xor_sync(0xFFFFFFFFu, v.y, m);
    v.z += __shfl_xor_sync(0xFFFFFFFFu, v.z, m);
    v.w += __shfl_xor_sync(0xFFFFFFFFu, v.w, m);
    return v;
}

// ---------------------------------------------------------------
// Input projection GEMM (also resets fr buffers + barrier flags):
//   out[m][n] = ALPHA * ( sum_k inp[m][k] * Win[n][k] + b_in[n] + b_hid[n] )
// ---------------------------------------------------------------
#define BM 64
#define BN 64
#define BK 32
#define TPAD 4

__global__ __launch_bounds__(256) void uproj_kernel(
    const float* __restrict__ inp, const float* __restrict__ Win,
    const float* __restrict__ b_in, const float* __restrict__ b_hid,
    float* __restrict__ out)
{
    if (blockIdx.x < 64) {
        float* p = (float*)g_fr;
        int base = (int)blockIdx.x * (2 * SBH / 64);
        for (int i = threadIdx.x; i < 2 * SBH / 64; i += 256) p[base + i] = 0.0f;
        if (blockIdx.x == 0 && threadIdx.x < R_GRID)
            g_flags[threadIdx.x * FLAG_STRIDE] = 0u;
    }

    __shared__ __align__(16) float As[BK][BM + TPAD];  // [k][m]
    __shared__ __align__(16) float Bs[BK][BN + TPAD];  // [k][n]

    const int tid = threadIdx.x;
    const int m0 = (int)(blockIdx.x >> 3) * BM;
    const int n0 = (int)(blockIdx.x & 7) * BN;
    const int tx = tid & 15;
    const int ty = tid >> 4;

    const float4* A4 = (const float4*)inp;   // [65536][32] float4
    const float4* B4 = (const float4*)Win;   // [512][32] float4

    float acc[4][4];
    #pragma unroll
    for (int i = 0; i < 4; i++)
        #pragma unroll
        for (int j = 0; j < 4; j++) acc[i][j] = 0.0f;

    for (int kc = 0; kc < IN_DIM / BK; kc++) {
        #pragma unroll
        for (int t = 0; t < 2; t++) {
            int j = tid + 256 * t;          // 0..511 float4s of 64x32 tile
            int m  = j >> 3;
            int kq = j & 7;
            float4 va = A4[(m0 + m) * 32 + kc * 8 + kq];
            As[kq * 4 + 0][m] = va.x; As[kq * 4 + 1][m] = va.y;
            As[kq * 4 + 2][m] = va.z; As[kq * 4 + 3][m] = va.w;
            float4 vb = B4[(n0 + m) * 32 + kc * 8 + kq];
            Bs[kq * 4 + 0][m] = vb.x; Bs[kq * 4 + 1][m] = vb.y;
            Bs[kq * 4 + 2][m] = vb.z; Bs[kq * 4 + 3][m] = vb.w;
        }
        __syncthreads();
        #pragma unroll
        for (int k = 0; k < BK; k++) {
            float4 a = *(const float4*)&As[k][ty * 4];
            float4 b = *(const float4*)&Bs[k][tx * 4];
            float av[4] = {a.x, a.y, a.z, a.w};
            float bv[4] = {b.x, b.y, b.z, b.w};
            #pragma unroll
            for (int i = 0; i < 4; i++)
                #pragma unroll
                for (int j2 = 0; j2 < 4; j2++)
                    acc[i][j2] += av[i] * bv[j2];
        }
        __syncthreads();
    }

    const int n = n0 + tx * 4;
    float bias0 = b_in[n + 0] + b_hid[n + 0];
    float bias1 = b_in[n + 1] + b_hid[n + 1];
    float bias2 = b_in[n + 2] + b_hid[n + 2];
    float bias3 = b_in[n + 3] + b_hid[n + 3];
    #pragma unroll
    for (int i = 0; i < 4; i++) {
        int m = m0 + ty * 4 + i;
        float4 o;
        o.x = ALPHA * (acc[i][0] + bias0);
        o.y = ALPHA * (acc[i][1] + bias1);
        o.z = ALPHA * (acc[i][2] + bias2);
        o.w = ALPHA * (acc[i][3] + bias3);
        *(float4*)&out[m * HID + n] = o;
    }
}

// ---------------------------------------------------------------
// Persistent recurrent kernel (512 threads = 16 warps).
// Warp wid owns k-sixteenth [32*wid, 32*wid+32). Lane = (hq, bq, kb):
// thread tile 4h x 4b x 2k. W and fr packed as (2x2k) 16B blocks so
// every dot load is a full 128B wavefront (256 MACs/wavefront).
// Per step per warp: poll 2 producer flags -> stage half, issue 2nd
// half LDGs, dot half, STS 2nd half, dot 2nd half -> kb shfl-merge ->
// partials to smem -> __syncthreads -> each warp shfl-tree reduces its
// own 4 output-float4s; owner lanes (0,16) hold v-state and store.
// Release via bar.arrive/bar.sync(1) so only warp 0 waits.
// ---------------------------------------------------------------
__global__ void __launch_bounds__(R_THREADS) rnn_kernel(
    const float* __restrict__ W_hid, float* __restrict__ out)
{
    extern __shared__ float4 smem[];
    float4* Ws  = smem;                 // [8][257] packed W (2h x 2k blocks)
    float4* Fs  = smem + W_F4;          // [8][257] packed fr (2b x 2k blocks)
    float4* red = smem + W_F4 + F_F4;   // [2][16][81] partials

    const int tid = threadIdx.x;
    const int bid = blockIdx.x;
    const int hg  = bid & 31;
    const int bg  = bid >> 5;
    const int h0  = hg * 16;
    const int b0  = bg * 16;

    const int wid = tid >> 5;          // warp = k-sixteenth 0..15
    const int l   = tid & 31;
    const int hq  = l & 3;             // 4h unit
    const int bq  = (l >> 2) & 3;      // 4b unit
    const int kb  = l >> 4;            // k sub-pair within iter
    const int sl  = l & 15;            // (hq,bq) slot id

    // ---- pack W: Ws[hp][kbg] = {W[h0+2hp][2kbg..+1], W[h0+2hp+1][2kbg..+1]} --
    const float2* wg2 = (const float2*)W_hid;   // [512][256] float2
    #pragma unroll
    for (int r = 0; r < 4; r++) {
        int idx = tid + 512 * r;       // 0..2047
        int hp  = idx >> 8;
        int kbg = idx & 255;
        float2 v0 = wg2[(h0 + 2 * hp)     * 256 + kbg];
        float2 v1 = wg2[(h0 + 2 * hp + 1) * 256 + kbg];
        Ws[hp * 257 + kbg] = make_float4(v0.x, v0.y, v1.x, v1.y);
    }
    __syncthreads();

    const int kbg0 = wid * 16;         // this warp's 16 k-pair blocks
    const float4* w0p = Ws + (2 * hq)     * 257 + kbg0 + kb;
    const float4* w1p = Ws + (2 * hq + 1) * 257 + kbg0 + kb;
    const float4* f0p = Fs + (2 * bq)     * 257 + kbg0 + kb;
    const float4* f1p = Fs + (2 * bq + 1) * 257 + kbg0 + kb;

    // Epilogue identity: warp wid owns slot sl==wid outputs.
    const int hb   = h0 + 4 * (wid & 3);
    const int ba   = b0 + 4 * (wid >> 2) + (l >> 4);   // lane0: +0, lane16: +1
    const int offA = ba * HID + hb;                     // b' = ba
    const int offC = (ba + 2) * HID + hb;               // b' = ba+2
    const bool owner = (sl == 0);                       // lanes 0 and 16

    float4 vA = make_float4(0, 0, 0, 0);
    float4 vC = make_float4(0, 0, 0, 0);

    const unsigned* poll =
        &g_flags[(((unsigned)bg << 5) + 2 * wid + (l & 1)) * FLAG_STRIDE];
    unsigned* myflag = &g_flags[bid * FLAG_STRIDE];

    for (int t = 0; t < SEQ; t++) {
        // DRAM prefetch of precomputed input terms (owner lanes only).
        float4 cA = make_float4(0, 0, 0, 0), cC = cA;
        if (owner) {
            cA = __ldcg((const float4*)&out[t * SBH + offA]);
            cC = __ldcg((const float4*)&out[t * SBH + offC]);
        }

        // ---- poll this sixteenth's 2 producers (4 lanes per flag) ----
        if (l < 8) {
            while (ld_acquire_gpu(poll) < (unsigned)t) { }
        }
        __syncwarp();

        // fr source for THIS CTA's batch group (b0 offset — the R14 bug fix)
        const float2* g2 = (const float2*)g_fr[t & 1] + (unsigned)b0 * 256;

        // ---- stage phase A (kbl 0..7): repack (2b x 2k) blocks ----
        #pragma unroll
        for (int j = 0; j < 2; j++) {
            int blk = l + 32 * j;              // 0..63
            int bp  = blk >> 3, kbl = blk & 7;
            float2 va = __ldcg(&g2[(2 * bp)     * 256 + kbg0 + kbl]);
            float2 vb = __ldcg(&g2[(2 * bp + 1) * 256 + kbg0 + kbl]);
            Fs[bp * 257 + kbg0 + kbl] = make_float4(va.x, va.y, vb.x, vb.y);
        }
        // ---- issue phase-B loads (in flight under dot A) ----
        int bpB0 = l >> 3,        kB0 = kbg0 + 8 + (l & 7);
        int bpB1 = (l + 32) >> 3, kB1 = kbg0 + 8 + ((l + 32) & 7);
        float2 b0a = __ldcg(&g2[(2 * bpB0)     * 256 + kB0]);
        float2 b0b = __ldcg(&g2[(2 * bpB0 + 1) * 256 + kB0]);
        float2 b1a = __ldcg(&g2[(2 * bpB1)     * 256 + kB1]);
        float2 b1b = __ldcg(&g2[(2 * bpB1 + 1) * 256 + kB1]);
        __syncwarp();

        // ---- dot: 16 f32x2 chains, phase A (iters 0..3) ----
        unsigned long long a[4][4];
        #pragma unroll
        for (int i = 0; i < 4; i++)
            #pragma unroll
            for (int j = 0; j < 4; j++) a[i][j] = 0ull;

        #pragma unroll
        for (int i = 0; i < 4; i++) {
            ulonglong2 w0 = *(const ulonglong2*)(w0p + 2 * i);
            ulonglong2 w1 = *(const ulonglong2*)(w1p + 2 * i);
            ulonglong2 f0 = *(const ulonglong2*)(f0p + 2 * i);
            ulonglong2 f1 = *(const ulonglong2*)(f1p + 2 * i);
            a[0][0] = ffma2(w0.x, f0.x, a[0][0]);
            a[0][1] = ffma2(w0.x, f0.y, a[0][1]);
            a[0][2] = ffma2(w0.x, f1.x, a[0][2]);
            a[0][3] = ffma2(w0.x, f1.y, a[0][3]);
            a[1][0] = ffma2(w0.y, f0.x, a[1][0]);
            a[1][1] = ffma2(w0.y, f0.y, a[1][1]);
            a[1][2] = ffma2(w0.y, f1.x, a[1][2]);
            a[1][3] = ffma2(w0.y, f1.y, a[1][3]);
            a[2][0] = ffma2(w1.x, f0.x, a[2][0]);
            a[2][1] = ffma2(w1.x, f0.y, a[2][1]);
            a[2][2] = ffma2(w1.x, f1.x, a[2][2]);
            a[2][3] = ffma2(w1.x, f1.y, a[2][3]);
            a[3][0] = ffma2(w1.y, f0.x, a[3][0]);
            a[3][1] = ffma2(w1.y, f0.y, a[3][1]);
            a[3][2] = ffma2(w1.y, f1.x, a[3][2]);
            a[3][3] = ffma2(w1.y, f1.y, a[3][3]);
        }

        // ---- store phase-B fr blocks, then dot phase B ----
        Fs[bpB0 * 257 + kB0] = make_float4(b0a.x, b0a.y, b0b.x, b0b.y);
        Fs[bpB1 * 257 + kB1] = make_float4(b1a.x, b1a.y, b1b.x, b1b.y);
        __syncwarp();

        #pragma unroll
        for (int i = 4; i < 8; i++) {
            ulonglong2 w0 = *(const ulonglong2*)(w0p + 2 * i);
            ulonglong2 w1 = *(const ulonglong2*)(w1p + 2 * i);
            ulonglong2 f0 = *(const ulonglong2*)(f0p + 2 * i);
            ulonglong2 f1 = *(const ulonglong2*)(f1p + 2 * i);
            a[0][0] = ffma2(w0.x, f0.x, a[0][0]);
            a[0][1] = ffma2(w0.x, f0.y, a[0][1]);
            a[0][2] = ffma2(w0.x, f1.x, a[0][2]);
            a[0][3] = ffma2(w0.x, f1.y, a[0][3]);
            a[1][0] = ffma2(w0.y, f0.x, a[1][0]);
            a[1][1] = ffma2(w0.y, f0.y, a[1][1]);
            a[1][2] = ffma2(w0.y, f1.x, a[1][2]);
            a[1][3] = ffma2(w0.y, f1.y, a[1][3]);
            a[2][0] = ffma2(w1.x, f0.x, a[2][0]);
            a[2][1] = ffma2(w1.x, f0.y, a[2][1]);
            a[2][2] = ffma2(w1.x, f1.x, a[2][2]);
            a[2][3] = ffma2(w1.x, f1.y, a[2][3]);
            a[3][0] = ffma2(w1.y, f0.x, a[3][0]);
            a[3][1] = ffma2(w1.y, f0.y, a[3][1]);
            a[3][2] = ffma2(w1.y, f1.x, a[3][2]);
            a[3][3] = ffma2(w1.y, f1.y, a[3][3]);
        }

        // ---- horizontal sums + kb merge (bfly 16) ----
        float s[4][4];
        #pragma unroll
        for (int i = 0; i < 4; i++)
            #pragma unroll
            for (int j = 0; j < 4; j++) {
                float v = f32x2_hadd(a[i][j]);
                v += __shfl_xor_sync(0xFFFFFFFFu, v, 16);
                s[i][j] = v;
            }

        // ---- write partials: lane half writes b' = {2*(l>>4), +1} ----
        {
            float4* rb = red + (t & 1) * (16 * 81) + wid * 81 + sl * 5
                             + 2 * (l >> 4);
            float4 p0, p1;
            if (l < 16) {
                p0 = make_float4(s[0][0], s[1][0], s[2][0], s[3][0]);
                p1 = make_float4(s[0][1], s[1][1], s[2][1], s[3][1]);
            } else {
                p0 = make_float4(s[0][2], s[1][2], s[2][2], s[3][2]);
                p1 = make_float4(s[0][3], s[1][3], s[2][3], s[3][3]);
            }
            rb[0] = p0;
            rb[1] = p1;
        }
        __syncthreads();   // all partials visible (single full sync per step)

        // ---- distributed reduce: warp wid reduces slot sl==wid ----
        {
            const float4* rr = red + (t & 1) * (16 * 81);
            int u  = sl;           // which warp's partial this lane reads
            int bA = l >> 4;       // b' base (0 or 1)
            float4 r0 = rr[u * 81 + wid * 5 + bA];
            float4 r1 = rr[u * 81 + wid * 5 + bA + 2];
            #pragma unroll
            for (int m = 1; m <= 8; m <<= 1) {
                r0 = shfl_xor_f4(r0, m);
                r1 = shfl_xor_f4(r1, m);
            }
            if (owner) {
                vA.x = 0.9f * vA.x + ALPHA * r0.x + cA.x;
                vA.y = 0.9f * vA.y + ALPHA * r0.y + cA.y;
                vA.z = 0.9f * vA.z + ALPHA * r0.z + cA.z;
                vA.w = 0.9f * vA.w + ALPHA * r0.w + cA.w;
                vC.x = 0.9f * vC.x + ALPHA * r1.x + cC.x;
                vC.y = 0.9f * vC.y + ALPHA * r1.y + cC.y;
                vC.z = 0.9f * vC.z + ALPHA * r1.z + cC.z;
                vC.w = 0.9f * vC.w + ALPHA * r1.w + cC.w;
                float4 fA = make_float4(fmaxf(vA.x, 0.f), fmaxf(vA.y, 0.f),
                                        fmaxf(vA.z, 0.f), fmaxf(vA.w, 0.f));
                float4 fC = make_float4(fmaxf(vC.x, 0.f), fmaxf(vC.y, 0.f),
                                        fmaxf(vC.z, 0.f), fmaxf(vC.w, 0.f));
                float* nxt = g_fr[(t + 1) & 1];
                __stcg((float4*)&nxt[offA], fA);        // publish next input
                __stcg((float4*)&nxt[offC], fC);
                __stcg((float4*)&out[t * SBH + offA], fA);   // state output
                __stcg((float4*)&out[t * SBH + offC], fC);
            }
        }

        // ---- release: only warp 0 waits for all stores, then signals ----
        if (wid == 0) {
            asm volatile("bar.sync 1, %0;" :: "n"(R_THREADS) : "memory");
            if (tid == 0) st_release_gpu(myflag, (unsigned)(t + 1));
        } else {
            asm volatile("bar.arrive 1, %0;" :: "n"(R_THREADS) : "memory");
        }
    }
}

// ---------------------------------------------------------------
// Launch — exactly two kernels so ncu's skip-5/capture-1 slot
// lands on rnn_kernel.
// ---------------------------------------------------------------
extern "C" void kernel_launch(void* const* d_in, const int* in_sizes, int n_in,
                              void* d_out, int out_size) {
    (void)in_sizes; (void)n_in; (void)out_size;
    const float* inp   = (const float*)d_in[0];   // (1024, 64, 128)
    const float* W_in  = (const float*)d_in[1];   // (512, 128)
    const float* b_in  = (const float*)d_in[2];   // (512,)
    const float* W_hid = (const float*)d_in[3];   // (512, 512)
    const float* b_hid = (const float*)d_in[4];   // (512,)
    float* out = (float*)d_out;                   // (1024, 64, 512)

    // u-proj GEMM (also resets fr buffers + barrier flags)
    uproj_kernel<<<8192, 256>>>(inp, W_in, b_in, b_hid, out);

    // Persistent recurrent kernel: 107264 B dynamic smem
    cudaFuncSetAttribute(rnn_kernel, cudaFuncAttributeMaxDynamicSharedMemorySize,
                         SMEM_BYTES);
    rnn_kernel<<<R_GRID, R_THREADS, SMEM_BYTES>>>(W_hid, out);
}